// round 4
// baseline (speedup 1.0000x reference)
#include <cuda_runtime.h>
#include <cstdint>
#include <cstddef>

// Fused e3nn per-irrep linear, tf32 mma.sync.
// R4: fragment-order SMEM (conflict-free, zero in-loop ALU), convert-once-at-fill,
// LDG->cvt->STS register pipeline, one __syncthreads per k-tile.
//   out[b, off + w*D + i] = PW * sum_u W[u,w] * x[b, off + u*D + i]  (+bias, D==1)

static constexpr int MUL   = 512;
static constexpr int DIM   = 4608;
static constexpr int BATCH = 4096;
static constexpr float PW  = 0.04419417382415922f;  // 512^-0.5
static constexpr int BN = 128;
static constexpr int BK = 16;
static constexpr int NK = MUL / BK;          // 32 k-tiles

// Fragment-order layout: float_idx = frow*36 + lane  (36 = 32 + 4 pad, kills STS conflicts)
// A: frow = (kkstep*NRB + rblock)*4 + (hi + 2*khi)   rblock=r/16, hi=(r>>3)&1
// B: frow = (kkstep*16  + nblock)*2 + khi            nblock=c/8
static constexpr int FR   = 36;
static constexpr int ASZ  = 2304;            // max A frag floats (NRB=8: 64 frows * 36)
static constexpr int BSZ  = 2304;            // 64 frows * 36
static constexpr int BUFF = ASZ + BSZ;       // 4608 floats per stage

__device__ __forceinline__ float to_tf32(float x) {
    asm("cvt.rna.tf32.f32 %0, %0;" : "+f"(x));
    return x;
}
__device__ __forceinline__ void mma_tf32(
    float& c0, float& c1, float& c2, float& c3,
    uint32_t a0, uint32_t a1, uint32_t a2, uint32_t a3,
    uint32_t b0, uint32_t b1)
{
    asm volatile(
        "mma.sync.aligned.m16n8k8.row.col.f32.tf32.tf32.f32 "
        "{%0,%1,%2,%3}, {%4,%5,%6,%7}, {%8,%9}, {%0,%1,%2,%3};"
        : "+f"(c0), "+f"(c1), "+f"(c2), "+f"(c3)
        : "r"(a0), "r"(a1), "r"(a2), "r"(a3), "r"(b0), "r"(b1));
}

template<int D, int R, int NWM, int NWN>
__device__ __forceinline__ void run_tile(
    const float* __restrict__ x, const float* __restrict__ w,
    const float* __restrict__ bias, float* __restrict__ out,
    int off, int mt, int nt, float* sm)
{
    constexpr int BM    = R / D;
    constexpr int WM    = R / NWM;
    constexpr int WN    = BN / NWN;
    constexpr int MFRAG = WM / 16;
    constexpr int NFRAG = WN / 8;
    constexpr int NRB   = R / 16;
    constexpr int NAV   = BM * BK * D / 4;   // A float4s per k-tile
    constexpr int NBV   = BK * BN / 4;       // 512 B float4s per k-tile
    static_assert(NWM * NWN == 8 && WM % 16 == 0 && WN % 8 == 0, "layout");

    const int tid  = threadIdx.x;
    const int wid  = tid >> 5;
    const int lane = tid & 31;
    const int g    = lane >> 2;
    const int tig  = lane & 3;
    const int wm   = wid % NWM;
    const int wn   = wid / NWM;
    const int b0   = mt * BM;
    const int w0   = nt * BN;

    // ---- precompute fill assignments (tile-invariant) ----
    const int nA = (tid + 256 < NAV) ? 2 : 1;   // every thread has >=1 (NAV>=320)
    const float* aptr[2];
    uint32_t aidx[2][4];                         // float indices into A frag region
    #pragma unroll
    for (int i = 0; i < 2; i++) {
        if (i < nA) {
            const int v  = tid + i * 256;
            const int bl = v / (BK * D / 4);
            const int jv = v % (BK * D / 4);
            aptr[i] = x + (size_t)(b0 + bl) * DIM + off + jv * 4;
            #pragma unroll
            for (int e = 0; e < 4; e++) {
                const int j = jv * 4 + e;
                const int k = j / D;
                const int i2 = j % D;
                const int r = bl * D + i2;
                const int frow = ((k >> 3) * NRB + (r >> 4)) * 4
                               + ((r >> 3) & 1) + 2 * ((k >> 2) & 1);
                aidx[i][e] = frow * FR + (r & 7) * 4 + (k & 3);
            }
        }
    }
    const float* bptr[2];
    uint32_t bidx[2];                            // element e at bidx + 4*e
    #pragma unroll
    for (int i = 0; i < 2; i++) {
        const int v = tid + i * 256;             // NBV = 512: exactly 2 each
        const int k = v >> 5;
        const int c = (v & 31) * 4;
        bptr[i] = w + (size_t)k * MUL + w0 + c;
        const int frow = ((k >> 3) * 16 + (c >> 3)) * 2 + ((k >> 2) & 1);
        bidx[i] = frow * FR + (c & 7) * 4 + (k & 3);
    }

    float acc[MFRAG][NFRAG][4] = {};
    float4 aval[2], bval[2];

    auto ldg = [&](int t) {
        #pragma unroll
        for (int i = 0; i < 2; i++)
            if (i < nA)
                aval[i] = *reinterpret_cast<const float4*>(aptr[i] + t * (BK * D));
        #pragma unroll
        for (int i = 0; i < 2; i++)
            bval[i] = *reinterpret_cast<const float4*>(bptr[i] + t * (BK * MUL));
    };

    // ---- prologue ----
    ldg(0);

    for (int t = 0; t < NK; t++) {
        float* Ab = sm + (t & 1) * BUFF;
        float* Bb = Ab + ASZ;

        // store stage t (convert once here)
        #pragma unroll
        for (int i = 0; i < 2; i++) {
            if (i < nA) {
                if constexpr (D == 1) {
                    float4 cv;
                    cv.x = to_tf32(aval[i].x); cv.y = to_tf32(aval[i].y);
                    cv.z = to_tf32(aval[i].z); cv.w = to_tf32(aval[i].w);
                    *reinterpret_cast<float4*>(&Ab[aidx[i][0]]) = cv;  // contiguous, 16B aligned
                } else {
                    Ab[aidx[i][0]] = to_tf32(aval[i].x);
                    Ab[aidx[i][1]] = to_tf32(aval[i].y);
                    Ab[aidx[i][2]] = to_tf32(aval[i].z);
                    Ab[aidx[i][3]] = to_tf32(aval[i].w);
                }
            }
        }
        #pragma unroll
        for (int i = 0; i < 2; i++) {
            Bb[bidx[i]     ] = to_tf32(bval[i].x);
            Bb[bidx[i] +  4] = to_tf32(bval[i].y);
            Bb[bidx[i] +  8] = to_tf32(bval[i].z);
            Bb[bidx[i] + 12] = to_tf32(bval[i].w);
        }
        __syncthreads();

        if (t + 1 < NK) ldg(t + 1);    // overlaps compute below

        // ---- compute: pure LDS + MMA, all addresses warp-const + lane*4 ----
        #pragma unroll
        for (int kkstep = 0; kkstep < 2; kkstep++) {
            uint32_t afr[MFRAG][4];
            #pragma unroll
            for (int m = 0; m < MFRAG; m++) {
                const int fb = (kkstep * NRB + wm * MFRAG + m) * 4;
                #pragma unroll
                for (int e = 0; e < 4; e++)
                    afr[m][e] = __float_as_uint(Ab[(fb + e) * FR + lane]);
            }
            uint32_t bfr[NFRAG][2];
            #pragma unroll
            for (int n = 0; n < NFRAG; n++) {
                const int fb = (kkstep * 16 + wn * NFRAG + n) * 2;
                bfr[n][0] = __float_as_uint(Bb[(fb    ) * FR + lane]);
                bfr[n][1] = __float_as_uint(Bb[(fb + 1) * FR + lane]);
            }
            #pragma unroll
            for (int m = 0; m < MFRAG; m++)
                #pragma unroll
                for (int n = 0; n < NFRAG; n++)
                    mma_tf32(acc[m][n][0], acc[m][n][1], acc[m][n][2], acc[m][n][3],
                             afr[m][0], afr[m][1], afr[m][2], afr[m][3],
                             bfr[n][0], bfr[n][1]);
        }
        // no second barrier: STS(t+1) targets the other buffer; the single
        // barrier already orders compute(t-1) (same buffer) before it.
        __syncthreads();
    }

    // ---- epilogue ----
    #pragma unroll
    for (int m = 0; m < MFRAG; m++) {
        #pragma unroll
        for (int half = 0; half < 2; half++) {
            const int row = wm * WM + m * 16 + g + half * 8;
            const int b   = b0 + row / D;
            const int i   = row % D;
            float* orow = out + (size_t)b * DIM + off + i;
            #pragma unroll
            for (int n = 0; n < NFRAG; n++) {
                const int col = wn * WN + n * 8 + 2 * tig;
                #pragma unroll
                for (int e = 0; e < 2; e++) {
                    const int wc = w0 + col + e;
                    float v = acc[m][n][half * 2 + e] * PW;
                    if (D == 1) v += bias[wc];
                    orow[(size_t)wc * D] = v;
                }
            }
        }
    }
}

// D=1 tile 128x128 -> 128 blocks; D=3 96x128 -> 512; D=5 80x128 -> 1024
static constexpr int NB0 = (BATCH / 128) * (MUL / BN);
static constexpr int NB1 = (BATCH / 32)  * (MUL / BN);
static constexpr int NB2 = (BATCH / 16)  * (MUL / BN);

__global__ __launch_bounds__(256, 2) void fused_irrep_kernel(
    const float* __restrict__ x,
    const float* __restrict__ w0, const float* __restrict__ w1,
    const float* __restrict__ w2, const float* __restrict__ b0,
    float* __restrict__ out)
{
    __shared__ __align__(16) float sm[2 * BUFF];   // 36,864 B
    const int bx = blockIdx.x;
    if (bx < NB0) {
        run_tile<1, 128, 2, 4>(x, w0, b0, out, 0,    bx >> 2, bx & 3, sm);
    } else if (bx < NB0 + NB1) {
        const int i = bx - NB0;
        run_tile<3,  96, 2, 4>(x, w1, b0, out, 512,  i >> 2, i & 3, sm);
    } else {
        const int i = bx - NB0 - NB1;
        run_tile<5,  80, 1, 8>(x, w2, b0, out, 2048, i >> 2, i & 3, sm);
    }
}

extern "C" void kernel_launch(void* const* d_in, const int* in_sizes, int n_in,
                              void* d_out, int out_size)
{
    const float* x  = (const float*)d_in[0];
    const float* w0 = (const float*)d_in[1];
    const float* w1 = (const float*)d_in[2];
    const float* w2 = (const float*)d_in[3];
    const float* b0 = (const float*)d_in[4];
    float* out = (float*)d_out;

    fused_irrep_kernel<<<NB0 + NB1 + NB2, 256>>>(x, w0, w1, w2, b0, out);
}

// round 6
// speedup vs baseline: 1.5434x; 1.5434x over previous
#include <cuda_runtime.h>
#include <cstdint>
#include <cstddef>

// Fused e3nn per-irrep linear, tf32 mma.sync (sm_103-safe PTX only).
// R6: ldmatrix.x4 A-fragments, zero in-loop cvt (HW tf32 truncation compensated
// by PWC), cp.async double-buffer with tile-invariant precomputed addresses.
//   out[b, off + w*D + i] = PW * sum_u W[u,w] * x[b, off + u*D + i]  (+bias, D==1)

static constexpr int MUL   = 512;
static constexpr int DIM   = 4608;
static constexpr int BATCH = 4096;
static constexpr int BN = 128;
static constexpr int BK = 16;
static constexpr int NK = MUL / BK;        // 32
// PW * (1 + 2^-10): compensates mean magnitude loss of fp32->tf32 truncation
// of BOTH operands (each (1-2^-11)).
static constexpr float PWC = 0.04423733224f;

static constexpr int LDKB   = 80;          // A row stride bytes (20 floats)
static constexpr int ABYTES = 128 * LDKB;  // max R=128 -> 10240 B
static constexpr int LDBF   = 136;         // B row stride floats
static constexpr int BBYTES = BK * LDBF * 4;  // 8704 B
static constexpr int STAGE  = ABYTES + BBYTES;

__device__ __forceinline__ void cp16(uint32_t s, const void* g) {
    asm volatile("cp.async.cg.shared.global [%0], [%1], 16;" :: "r"(s), "l"(g));
}
__device__ __forceinline__ void cp4(uint32_t s, const void* g) {
    asm volatile("cp.async.ca.shared.global [%0], [%1], 4;" :: "r"(s), "l"(g));
}
__device__ __forceinline__ void cp_commit() {
    asm volatile("cp.async.commit_group;" ::: "memory");
}
__device__ __forceinline__ void cp_wait1() {
    asm volatile("cp.async.wait_group 1;" ::: "memory");
}
__device__ __forceinline__ void ldmx4(uint32_t& r0, uint32_t& r1, uint32_t& r2,
                                      uint32_t& r3, uint32_t addr) {
    asm volatile("ldmatrix.sync.aligned.m8n8.x4.shared.b16 {%0,%1,%2,%3}, [%4];"
                 : "=r"(r0), "=r"(r1), "=r"(r2), "=r"(r3) : "r"(addr));
}
__device__ __forceinline__ float lds_f(uint32_t addr) {
    float v;
    asm volatile("ld.shared.f32 %0, [%1];" : "=f"(v) : "r"(addr));
    return v;
}
__device__ __forceinline__ void mma_tf32(
    float& c0, float& c1, float& c2, float& c3,
    uint32_t a0, uint32_t a1, uint32_t a2, uint32_t a3,
    uint32_t b0, uint32_t b1)
{
    asm volatile(
        "mma.sync.aligned.m16n8k8.row.col.f32.tf32.tf32.f32 "
        "{%0,%1,%2,%3}, {%4,%5,%6,%7}, {%8,%9}, {%0,%1,%2,%3};"
        : "+f"(c0), "+f"(c1), "+f"(c2), "+f"(c3)
        : "r"(a0), "r"(a1), "r"(a2), "r"(a3), "r"(b0), "r"(b1));
}

template<int D, int R, int NWM, int NWN>
__device__ __forceinline__ void run_tile(
    const float* __restrict__ x, const float* __restrict__ w,
    const float* __restrict__ bias, float* __restrict__ out,
    int mt, int nt, int off, uint32_t smb)
{
    constexpr int BM    = R / D;
    constexpr int WM    = R / NWM;
    constexpr int WN    = BN / NWN;
    constexpr int MFRAG = WM / 16;
    constexpr int NFRAG = WN / 8;
    constexpr int NA    = (D == 1) ? 2 : (BM * BK * D / 256);  // fill entries/thread
    static_assert(NWM * NWN == 8 && WM % 16 == 0 && WN % 8 == 0, "layout");

    const int tid  = threadIdx.x;
    const int wid  = tid >> 5;
    const int lane = tid & 31;
    const int g    = lane >> 2;
    const int tig  = lane & 3;
    const int wm   = wid % NWM;
    const int wn   = wid / NWM;
    const int b0   = mt * BM;
    const int w0   = nt * BN;

    // ---- tile-invariant fill assignments ----
    const float* const xb = x + (size_t)b0 * DIM + off;
    int      aoffg[NA];     // global float offset (rel xb), advance BK*D per tile
    uint32_t aoffs[NA];     // smem byte offset within A region
    #pragma unroll
    for (int e = 0; e < NA; e++) {
        const int v = tid + e * 256;
        if constexpr (D == 1) {
            const int r = v >> 2, ch = v & 3;
            aoffg[e] = r * DIM + ch * 4;
            aoffs[e] = (uint32_t)(r * LDKB + ch * 16);
        } else {
            const int bl = v / (BK * D);
            const int j  = v % (BK * D);
            const int k  = j / D;
            const int r  = bl * D + j % D;
            aoffg[e] = bl * DIM + j;
            aoffs[e] = (uint32_t)(r * LDKB + k * 4);
        }
    }
    const float* const wb = w + w0;
    int      boffg[2];
    uint32_t boffs[2];
    #pragma unroll
    for (int e = 0; e < 2; e++) {
        const int v = tid + e * 256;
        const int k = v >> 5, ch = v & 31;
        boffg[e] = k * MUL + ch * 4;
        boffs[e] = (uint32_t)(k * LDBF * 4 + ch * 16);
    }
    // ldmatrix per-lane row assignment (invariant)
    const int rowadd = (lane & 7) + ((lane >> 3) & 1) * 8;
    const int hi16   = (lane >> 4) * 16;

    float acc[MFRAG][NFRAG][4] = {};

    auto load_tile = [&](int t, uint32_t Abase, uint32_t Bbase) {
        const int ta = t * (BK * D);
        #pragma unroll
        for (int e = 0; e < NA; e++) {
            if constexpr (D == 1) cp16(Abase + aoffs[e], xb + aoffg[e] + ta);
            else                  cp4 (Abase + aoffs[e], xb + aoffg[e] + ta);
        }
        const int tb = t * (BK * MUL);
        #pragma unroll
        for (int e = 0; e < 2; e++)
            cp16(Bbase + boffs[e], wb + boffg[e] + tb);
    };

    const uint32_t A0 = smb, B0 = smb + ABYTES;
    load_tile(0, A0, B0);
    cp_commit();

    for (int t = 0; t < NK; t++) {
        const uint32_t Ac = smb + (t & 1) * STAGE;
        const uint32_t Bc = Ac + ABYTES;
        if (t + 1 < NK) {
            const uint32_t An = smb + ((t + 1) & 1) * STAGE;
            load_tile(t + 1, An, An + ABYTES);
        }
        cp_commit();
        cp_wait1();
        __syncthreads();

        #pragma unroll
        for (int kk = 0; kk < BK; kk += 8) {
            uint32_t afr[MFRAG][4];
            #pragma unroll
            for (int m = 0; m < MFRAG; m++) {
                const uint32_t a = Ac + (uint32_t)((wm * WM + m * 16 + rowadd) * LDKB
                                                   + kk * 4 + hi16);
                ldmx4(afr[m][0], afr[m][1], afr[m][2], afr[m][3], a);
            }
            uint32_t bfr[NFRAG][2];
            #pragma unroll
            for (int n = 0; n < NFRAG; n++) {
                const uint32_t f = Bc + (uint32_t)(((kk + tig) * LDBF
                                                   + wn * WN + n * 8 + g) * 4);
                bfr[n][0] = __float_as_uint(lds_f(f));
                bfr[n][1] = __float_as_uint(lds_f(f + 4 * LDBF * 4));
            }
            #pragma unroll
            for (int m = 0; m < MFRAG; m++)
                #pragma unroll
                for (int n = 0; n < NFRAG; n++)
                    mma_tf32(acc[m][n][0], acc[m][n][1], acc[m][n][2], acc[m][n][3],
                             afr[m][0], afr[m][1], afr[m][2], afr[m][3],
                             bfr[n][0], bfr[n][1]);
        }
        __syncthreads();
    }

    // ---- epilogue (truncation compensation folded into PWC) ----
    #pragma unroll
    for (int m = 0; m < MFRAG; m++) {
        #pragma unroll
        for (int half = 0; half < 2; half++) {
            const int row = wm * WM + m * 16 + g + half * 8;
            const int b   = b0 + row / D;
            const int i   = row % D;
            float* orow = out + (size_t)b * DIM + off + i;
            #pragma unroll
            for (int n = 0; n < NFRAG; n++) {
                const int col = wn * WN + n * 8 + 2 * tig;
                #pragma unroll
                for (int e = 0; e < 2; e++) {
                    const int wc = w0 + col + e;
                    float v = acc[m][n][half * 2 + e] * PWC;
                    if (D == 1) v += bias[wc];
                    orow[(size_t)wc * D] = v;
                }
            }
        }
    }
}

// D=1 tile 128x128 -> 128 blocks; D=3 96x128 -> 512; D=5 80x128 -> 1024
static constexpr int NB0 = (BATCH / 128) * (MUL / BN);
static constexpr int NB1 = (BATCH / 32)  * (MUL / BN);
static constexpr int NB2 = (BATCH / 16)  * (MUL / BN);

__global__ __launch_bounds__(256, 2) void fused_irrep_kernel(
    const float* __restrict__ x,
    const float* __restrict__ w0, const float* __restrict__ w1,
    const float* __restrict__ w2, const float* __restrict__ b0,
    float* __restrict__ out)
{
    __shared__ __align__(16) char sm[2 * STAGE];   // 37,888 B
    const uint32_t smb = (uint32_t)__cvta_generic_to_shared(sm);
    const int bx = blockIdx.x;
    if (bx < NB0) {
        run_tile<1, 128, 2, 4>(x, w0, b0, out, bx >> 2, bx & 3, 0, smb);
    } else if (bx < NB0 + NB1) {
        const int i = bx - NB0;
        run_tile<3,  96, 2, 4>(x, w1, b0, out, i >> 2, i & 3, 512, smb);
    } else {
        const int i = bx - NB0 - NB1;
        run_tile<5,  80, 1, 8>(x, w2, b0, out, i >> 2, i & 3, 2048, smb);
    }
}

extern "C" void kernel_launch(void* const* d_in, const int* in_sizes, int n_in,
                              void* d_out, int out_size)
{
    const float* x  = (const float*)d_in[0];
    const float* w0 = (const float*)d_in[1];
    const float* w1 = (const float*)d_in[2];
    const float* w2 = (const float*)d_in[3];
    const float* b0 = (const float*)d_in[4];
    float* out = (float*)d_out;

    fused_irrep_kernel<<<NB0 + NB1 + NB2, 256>>>(x, w0, w1, w2, b0, out);
}